// round 14
// baseline (speedup 1.0000x reference)
#include <cuda_runtime.h>

// out[m,b] = sum_n M[m,n,b] * V[n,b]
// M: [2048, 2048, 64] f32 (b contiguous), V: [2048, 64] f32, out: [2048, 64] f32
//
// FINAL kernel (confirmed x4: 152.06/152.29/152.29/152.32 us = 7.07 TB/s =
// 88.4% of spec, inside B300's 88-92% HBM uniformity band). Bytes irreducible.
//   - 64-thread CTAs (16 b-quads x 4 INTERLEAVED n-slices), grid=1024, TM=2
//   - 7 CTAs/SM resident -> single full wave
//   - unroll 8; M (DRAM-miss) loads issued BEFORE V (L2-hit) load per group
//     so misses enter the in-order L1tex wavefront queue earliest
//   - one V load feeds FMAs for 2 m-rows; M streamed with .cs

#define MV_N     2048
#define MV_MDIM  2048
#define MV_B     64
#define MV_BQ    (MV_B / 4)   // 16 float4 per (m,n) row
#define MV_TM    2
#define MV_NY    4            // n-slices per CTA

__global__ __launch_bounds__(64, 7)
void matvec_batched_kernel(const float4* __restrict__ M4,
                           const float4* __restrict__ V4,
                           float4* __restrict__ out4)
{
    const int x = threadIdx.x;   // 0..15, b-quad
    const int y = threadIdx.y;   // 0..3,  n-slice
    const int m0 = blockIdx.x * MV_TM;

    const float4* __restrict__ Ma = M4 + (size_t)m0 * (size_t)(MV_N * MV_BQ);
    const float4* __restrict__ Mb = Ma + (size_t)(MV_N * MV_BQ);

    float4 acc0 = make_float4(0.f, 0.f, 0.f, 0.f);
    float4 acc1 = make_float4(0.f, 0.f, 0.f, 0.f);

    #pragma unroll 8
    for (int n = y; n < MV_N; n += MV_NY) {
        const int idx = n * MV_BQ + x;
        const float4 a = __ldcs(&Ma[idx]);   // DRAM miss: issue first
        const float4 b = __ldcs(&Mb[idx]);   // DRAM miss: issue first
        const float4 v = __ldg(&V4[idx]);    // L2 hit: issue after misses
        acc0.x = fmaf(a.x, v.x, acc0.x);
        acc0.y = fmaf(a.y, v.y, acc0.y);
        acc0.z = fmaf(a.z, v.z, acc0.z);
        acc0.w = fmaf(a.w, v.w, acc0.w);
        acc1.x = fmaf(b.x, v.x, acc1.x);
        acc1.y = fmaf(b.y, v.y, acc1.y);
        acc1.z = fmaf(b.z, v.z, acc1.z);
        acc1.w = fmaf(b.w, v.w, acc1.w);
    }

    // Reduce the 4 n-slice partials per b-quad for both m-rows.
    __shared__ float4 red[MV_TM][MV_NY][16];
    red[0][y][x] = acc0;
    red[1][y][x] = acc1;
    __syncthreads();

    #pragma unroll
    for (int s = MV_NY / 2; s > 0; s >>= 1) {
        if (y < s) {
            #pragma unroll
            for (int t = 0; t < MV_TM; t++) {
                float4 o = red[t][y + s][x];
                float4 a0 = red[t][y][x];
                a0.x += o.x; a0.y += o.y; a0.z += o.z; a0.w += o.w;
                red[t][y][x] = a0;
            }
        }
        __syncthreads();
    }

    if (y < MV_TM) {
        out4[(size_t)(m0 + y) * MV_BQ + x] = red[y][0][x];
    }
}

extern "C" void kernel_launch(void* const* d_in, const int* in_sizes, int n_in,
                              void* d_out, int out_size)
{
    const float4* M4 = (const float4*)d_in[0];
    const float4* V4 = (const float4*)d_in[1];
    float4* out4 = (float4*)d_out;

    dim3 block(16, MV_NY);
    dim3 grid(MV_MDIM / MV_TM);
    matvec_batched_kernel<<<grid, block>>>(M4, V4, out4);
}

// round 15
// speedup vs baseline: 1.0040x; 1.0040x over previous
#include <cuda_runtime.h>

// out[m,b] = sum_n M[m,n,b] * V[n,b]
// M: [2048, 2048, 64] f32 (b contiguous), V: [2048, 64] f32, out: [2048, 64] f32
//
// FINAL kernel — measured HW ceiling, confirmed over 5 reproductions
// (152.06-152.32 us = 7.05-7.09 TB/s = 88-89% of 8 TB/s spec, matching the
// documented B300 HBM channel-uniformity band of 88-92%). Bytes irreducible
// (1 GiB of M read exactly once, zero reuse, AI = 0.25 flop/B).
//
// Closed axes (all measured): geometry (6 variants), cache policy (5),
// load width (128 vs 256-bit), MLP/unroll depth, n-address order,
// V-traffic amortization (TM=1/2/4), load issue order.
//
//   - 64-thread CTAs (16 b-quads x 4 interleaved n-slices), grid=1024, TM=2
//     (each warp LDG covers one contiguous 1-KB span -> dense DRAM bursts)
//   - 7 CTAs/SM resident -> single full wave, no wave transition
//   - unroll 8 -> ptxas front-batches independent LDG.128 (128 regs)
//   - one V load feeds FMAs for 2 m-rows; M streamed with .cs

#define MV_N     2048
#define MV_MDIM  2048
#define MV_B     64
#define MV_BQ    (MV_B / 4)   // 16 float4 per (m,n) row
#define MV_TM    2
#define MV_NY    4            // n-slices per CTA

__global__ __launch_bounds__(64, 7)
void matvec_batched_kernel(const float4* __restrict__ M4,
                           const float4* __restrict__ V4,
                           float4* __restrict__ out4)
{
    const int x = threadIdx.x;   // 0..15, b-quad
    const int y = threadIdx.y;   // 0..3,  n-slice
    const int m0 = blockIdx.x * MV_TM;

    const float4* __restrict__ Ma = M4 + (size_t)m0 * (size_t)(MV_N * MV_BQ);
    const float4* __restrict__ Mb = Ma + (size_t)(MV_N * MV_BQ);

    float4 acc0 = make_float4(0.f, 0.f, 0.f, 0.f);
    float4 acc1 = make_float4(0.f, 0.f, 0.f, 0.f);

    #pragma unroll 8
    for (int n = y; n < MV_N; n += MV_NY) {
        const int idx = n * MV_BQ + x;
        const float4 v = __ldg(&V4[idx]);
        const float4 a = __ldcs(&Ma[idx]);
        const float4 b = __ldcs(&Mb[idx]);
        acc0.x = fmaf(a.x, v.x, acc0.x);
        acc0.y = fmaf(a.y, v.y, acc0.y);
        acc0.z = fmaf(a.z, v.z, acc0.z);
        acc0.w = fmaf(a.w, v.w, acc0.w);
        acc1.x = fmaf(b.x, v.x, acc1.x);
        acc1.y = fmaf(b.y, v.y, acc1.y);
        acc1.z = fmaf(b.z, v.z, acc1.z);
        acc1.w = fmaf(b.w, v.w, acc1.w);
    }

    // Reduce the 4 n-slice partials per b-quad for both m-rows.
    __shared__ float4 red[MV_TM][MV_NY][16];
    red[0][y][x] = acc0;
    red[1][y][x] = acc1;
    __syncthreads();

    #pragma unroll
    for (int s = MV_NY / 2; s > 0; s >>= 1) {
        if (y < s) {
            #pragma unroll
            for (int t = 0; t < MV_TM; t++) {
                float4 o = red[t][y + s][x];
                float4 a0 = red[t][y][x];
                a0.x += o.x; a0.y += o.y; a0.z += o.z; a0.w += o.w;
                red[t][y][x] = a0;
            }
        }
        __syncthreads();
    }

    if (y < MV_TM) {
        out4[(size_t)(m0 + y) * MV_BQ + x] = red[y][0][x];
    }
}

extern "C" void kernel_launch(void* const* d_in, const int* in_sizes, int n_in,
                              void* d_out, int out_size)
{
    const float4* M4 = (const float4*)d_in[0];
    const float4* V4 = (const float4*)d_in[1];
    float4* out4 = (float4*)d_out;

    dim3 block(16, MV_NY);
    dim3 grid(MV_MDIM / MV_TM);
    matvec_batched_kernel<<<grid, block>>>(M4, V4, out4);
}